// round 4
// baseline (speedup 1.0000x reference)
#include <cuda_runtime.h>
#include <math_constants.h>

#define B 16
#define T 32
#define WW 128
#define D 1024
#define NDBLK 32            // d-chunks for projection partials
#define DCHUNK (D / NDBLK)  // 32

// Scratch (no device allocation allowed). .bss is zero-initialized: masked-turn
// rows of g_cw are never written and stay exactly 0 across graph replays.
__device__ float g_part[2 * NDBLK * B * D];  // 4 MB
__device__ float g_q[2 * B * D];
__device__ float g_cw[B * T * D];
__device__ float g_ts[B * T];

// ---------------------------------------------------------------------------
// Kernel 1: partial projections q = source @ W (W stored [indim, outdim]).
// grid = (NDBLK, 1, 2 mats) = 64 CTAs, 256 threads. One CTA covers ALL 16
// batch rows -> W is read exactly once (8 MB total).
// ---------------------------------------------------------------------------
__global__ __launch_bounds__(256) void proj_part_kernel(
    const float* __restrict__ src, const float* __restrict__ Wword,
    const float* __restrict__ Wturn) {
  int dblk = blockIdx.x;
  int mat = blockIdx.z;
  const float* __restrict__ Wm = mat ? Wturn : Wword;
  int c4 = threadIdx.x * 4;
  int d0 = dblk * DCHUNK;

  __shared__ float s_src[DCHUNK][B];  // 32 x 16
#pragma unroll
  for (int e = threadIdx.x; e < DCHUNK * B; e += 256) {
    int dl = e >> 4, bb = e & 15;
    s_src[dl][bb] = src[bb * D + d0 + dl];
  }
  __syncthreads();

  float4 acc[B];
#pragma unroll
  for (int bb = 0; bb < B; bb++) acc[bb] = make_float4(0.f, 0.f, 0.f, 0.f);

#pragma unroll
  for (int dl = 0; dl < DCHUNK; dl++) {
    float4 wv = *reinterpret_cast<const float4*>(&Wm[(d0 + dl) * D + c4]);
#pragma unroll
    for (int bb = 0; bb < B; bb++) {
      float s = s_src[dl][bb];
      acc[bb].x = fmaf(s, wv.x, acc[bb].x);
      acc[bb].y = fmaf(s, wv.y, acc[bb].y);
      acc[bb].z = fmaf(s, wv.z, acc[bb].z);
      acc[bb].w = fmaf(s, wv.w, acc[bb].w);
    }
  }

#pragma unroll
  for (int bb = 0; bb < B; bb++) {
    float* outp = g_part + ((long)(mat * NDBLK + dblk) * B + bb) * D + c4;
    *reinterpret_cast<float4*>(outp) = acc[bb];
  }
}

// ---------------------------------------------------------------------------
// Kernel 2: reduce NDBLK partials -> g_q[2][B][D]. grid = 32 x 256 (4 MB read).
// Tree accumulation in 4 partials so loads can batch wide.
// ---------------------------------------------------------------------------
__global__ __launch_bounds__(256) void reduce_q_kernel() {
  int idx = blockIdx.x * 256 + threadIdx.x;  // [2][16][256 float4]
  int mat = idx >> 12;
  int b = (idx >> 8) & 15;
  int c4 = (idx & 255) * 4;
  float4 s0 = make_float4(0.f, 0.f, 0.f, 0.f), s1 = s0, s2 = s0, s3 = s0;
#pragma unroll
  for (int j = 0; j < NDBLK; j += 4) {
    const float* bp = g_part + ((long)(mat * NDBLK + j) * B + b) * D + c4;
    float4 p0 = *reinterpret_cast<const float4*>(bp);
    float4 p1 = *reinterpret_cast<const float4*>(bp + (long)B * D);
    float4 p2 = *reinterpret_cast<const float4*>(bp + 2L * B * D);
    float4 p3 = *reinterpret_cast<const float4*>(bp + 3L * B * D);
    s0.x += p0.x; s0.y += p0.y; s0.z += p0.z; s0.w += p0.w;
    s1.x += p1.x; s1.y += p1.y; s1.z += p1.z; s1.w += p1.w;
    s2.x += p2.x; s2.y += p2.y; s2.z += p2.z; s2.w += p2.w;
    s3.x += p3.x; s3.y += p3.y; s3.z += p3.z; s3.w += p3.w;
  }
  float4 sum = make_float4(s0.x + s1.x + s2.x + s3.x, s0.y + s1.y + s2.y + s3.y,
                           s0.z + s1.z + s2.z + s3.z, s0.w + s1.w + s2.w + s3.w);
  *reinterpret_cast<float4*>(g_q + (mat * B + b) * D + c4) = sum;
}

// ---------------------------------------------------------------------------
// Kernel 3: per-(b,t) word attention. 128 threads (4 warps), warp-private
// online softmax, rows strided by 4, cur/nxt software pipeline: the next
// row's loads are issued BEFORE the shfl-reduce/exp chain of the current row.
// ---------------------------------------------------------------------------
__global__ __launch_bounds__(128) void attn_kernel(
    const float* __restrict__ bank, const int* __restrict__ lens,
    const int* __restrict__ turns) {
  int t = blockIdx.x, b = blockIdx.y;
  if (t >= turns[b]) return;  // masked turn: contributes exactly 0 downstream
  int len = lens[b * T + t];
  int tid = threadIdx.x, wp = tid >> 5, lane = tid & 31;

  // lane owns cols j*128 + lane*4, j = 0..7 (full D per warp)
  float4 qw[8];
#pragma unroll
  for (int j = 0; j < 8; j++)
    qw[j] = *reinterpret_cast<const float4*>(g_q + b * D + j * 128 + lane * 4);

  const float* __restrict__ base = bank + (long)(b * T + t) * WW * D;

  float m = -CUDART_INF_F, ssum = 0.f;
  float4 acc[8];
#pragma unroll
  for (int j = 0; j < 8; j++) acc[j] = make_float4(0.f, 0.f, 0.f, 0.f);

  int w = wp;  // 0..3; row w < WW always a valid address
  float4 cur[8], nxt[8];
#pragma unroll
  for (int j = 0; j < 8; j++)
    cur[j] = *reinterpret_cast<const float4*>(base + w * D + j * 128 + lane * 4);

#pragma unroll 1
  for (; w < len; w += 4) {
    // prefetch next row (dummy row 0 when out of range -> L2 hit, discarded)
    int wn = (w + 4 < len) ? (w + 4) : 0;
    const float* nb = base + wn * D;
#pragma unroll
    for (int j = 0; j < 8; j++)
      nxt[j] = *reinterpret_cast<const float4*>(nb + j * 128 + lane * 4);

    float p = 0.f;
#pragma unroll
    for (int j = 0; j < 8; j++)
      p = fmaf(qw[j].x, cur[j].x, fmaf(qw[j].y, cur[j].y,
          fmaf(qw[j].z, cur[j].z, fmaf(qw[j].w, cur[j].w, p))));
#pragma unroll
    for (int off = 16; off; off >>= 1) p += __shfl_xor_sync(0xffffffffu, p, off);

    float mnew = fmaxf(m, p);
    float sc = __expf(m - mnew);  // 0 on first row (m = -inf)
    float e = __expf(p - mnew);
    ssum = fmaf(ssum, sc, e);
    m = mnew;
#pragma unroll
    for (int j = 0; j < 8; j++) {
      acc[j].x = fmaf(e, cur[j].x, acc[j].x * sc);
      acc[j].y = fmaf(e, cur[j].y, acc[j].y * sc);
      acc[j].z = fmaf(e, cur[j].z, acc[j].z * sc);
      acc[j].w = fmaf(e, cur[j].w, acc[j].w * sc);
    }
#pragma unroll
    for (int j = 0; j < 8; j++) cur[j] = nxt[j];
  }

  // ---- merge 4 warp-private (m, ssum, acc) states ----
  __shared__ float s_ms[4][2];
  __shared__ __align__(16) float s_acc[4][D];  // 16 KB
  if (lane == 0) { s_ms[wp][0] = m; s_ms[wp][1] = ssum; }
  __syncthreads();
  float M = -CUDART_INF_F;
#pragma unroll
  for (int k = 0; k < 4; k++) M = fmaxf(M, s_ms[k][0]);
  float S = 0.f;
#pragma unroll
  for (int k = 0; k < 4; k++) S += s_ms[k][1] * __expf(s_ms[k][0] - M);
  float wt = __expf(m - M);  // 0 for warps that saw no rows (m = -inf)
#pragma unroll
  for (int j = 0; j < 8; j++) {
    float4 v = make_float4(acc[j].x * wt, acc[j].y * wt, acc[j].z * wt, acc[j].w * wt);
    *reinterpret_cast<float4*>(&s_acc[wp][j * 128 + lane * 4]) = v;
  }
  __syncthreads();

  // each thread finalizes 2 float4 (128 threads x 8 floats = D)
  float inv = 1.f / S;
  float tp = 0.f;
#pragma unroll
  for (int h = 0; h < 2; h++) {
    int c4 = tid * 8 + h * 4;
    float4 sum = make_float4(0.f, 0.f, 0.f, 0.f);
#pragma unroll
    for (int k = 0; k < 4; k++) {
      float4 v = *reinterpret_cast<const float4*>(&s_acc[k][c4]);
      sum.x += v.x; sum.y += v.y; sum.z += v.z; sum.w += v.w;
    }
    float4 cw = make_float4(sum.x * inv, sum.y * inv, sum.z * inv, sum.w * inv);
    *reinterpret_cast<float4*>(g_cw + (b * T + t) * D + c4) = cw;
    float4 qt = *reinterpret_cast<const float4*>(g_q + (B + b) * D + c4);
    tp = fmaf(qt.x, cw.x, fmaf(qt.y, cw.y, fmaf(qt.z, cw.z, fmaf(qt.w, cw.w, tp))));
  }
#pragma unroll
  for (int off = 16; off; off >>= 1) tp += __shfl_down_sync(0xffffffffu, tp, off);
  if (lane == 0) s_ms[wp][0] = tp;  // s_ms reads all completed before 2nd barrier
  __syncthreads();
  if (tid == 0)
    g_ts[b * T + t] = s_ms[0][0] + s_ms[1][0] + s_ms[2][0] + s_ms[3][0];
}

// ---------------------------------------------------------------------------
// Kernel 4: turn softmax + combine. grid = (4 col-chunks, B) = 64 CTAs,
// 256 threads: tid -> (turn-group tg = tid>>6 of 8 turns, float4 col c).
// smem tree-reduce across the 4 turn groups. Masked turns: weight exactly 0
// and g_cw rows exactly 0 -> no NaN risk.
// ---------------------------------------------------------------------------
__global__ __launch_bounds__(256) void combine_kernel(
    const int* __restrict__ turns, float* __restrict__ out) {
  int b = blockIdx.y;
  int chunk = blockIdx.x;
  int nt = turns[b];
  int tid = threadIdx.x;
  __shared__ float attw[T];
  __shared__ __align__(16) float s_red[4][256];
  if (tid < 32) {  // T == 32
    float s = (tid < nt) ? g_ts[b * T + tid] : -CUDART_INF_F;
    float mx = s;
#pragma unroll
    for (int off = 16; off; off >>= 1)
      mx = fmaxf(mx, __shfl_xor_sync(0xffffffffu, mx, off));
    float e = (tid < nt) ? __expf(s - mx) : 0.f;
    float sm = e;
#pragma unroll
    for (int off = 16; off; off >>= 1)
      sm += __shfl_xor_sync(0xffffffffu, sm, off);
    attw[tid] = e / sm;
  }
  __syncthreads();

  int c = tid & 63;   // float4 index within the 256-col chunk
  int tg = tid >> 6;  // 0..3 -> turns tg*8 .. tg*8+7
  int c4 = chunk * 256 + c * 4;
  float4 acc = make_float4(0.f, 0.f, 0.f, 0.f);
#pragma unroll
  for (int i = 0; i < 8; i++) {
    int t = tg * 8 + i;
    float a = attw[t];
    float4 cw = *reinterpret_cast<const float4*>(g_cw + (b * T + t) * D + c4);
    acc.x = fmaf(a, cw.x, acc.x);
    acc.y = fmaf(a, cw.y, acc.y);
    acc.z = fmaf(a, cw.z, acc.z);
    acc.w = fmaf(a, cw.w, acc.w);
  }
  *reinterpret_cast<float4*>(&s_red[tg][c * 4]) = acc;
  __syncthreads();
  if (tg == 0) {
    float4 r0 = *reinterpret_cast<const float4*>(&s_red[0][c * 4]);
    float4 r1 = *reinterpret_cast<const float4*>(&s_red[1][c * 4]);
    float4 r2 = *reinterpret_cast<const float4*>(&s_red[2][c * 4]);
    float4 r3 = *reinterpret_cast<const float4*>(&s_red[3][c * 4]);
    float4 o = make_float4(r0.x + r1.x + r2.x + r3.x, r0.y + r1.y + r2.y + r3.y,
                           r0.z + r1.z + r2.z + r3.z, r0.w + r1.w + r2.w + r3.w);
    *reinterpret_cast<float4*>(out + b * D + c4) = o;
  }
}

// ---------------------------------------------------------------------------
extern "C" void kernel_launch(void* const* d_in, const int* in_sizes, int n_in,
                              void* d_out, int out_size) {
  const float *src = nullptr, *bank = nullptr, *Wword = nullptr, *Wturn = nullptr;
  const int *lens = nullptr, *turns = nullptr;
  for (int i = 0; i < n_in; i++) {
    switch (in_sizes[i]) {
      case B * D:            src  = (const float*)d_in[i]; break;
      case B * T * WW * D:   bank = (const float*)d_in[i]; break;
      case B * T:            lens = (const int*)d_in[i];   break;
      case B:                turns = (const int*)d_in[i];  break;
      case D * D:
        if (!Wword) Wword = (const float*)d_in[i];
        else        Wturn = (const float*)d_in[i];
        break;
      default: break;
    }
  }
  proj_part_kernel<<<dim3(NDBLK, 1, 2), 256>>>(src, Wword, Wturn);
  reduce_q_kernel<<<32, 256>>>();
  attn_kernel<<<dim3(T, B), 128>>>(bank, lens, turns);
  combine_kernel<<<dim3(4, B), 256>>>(turns, (float*)d_out);
}